// round 12
// baseline (speedup 1.0000x reference)
#include <cuda_runtime.h>

#define NB      2
#define CC      512
#define SS      256
#define DCHUNK  64
#define NKCH    8
#define THREADS 512
#define WARPS   16

#define CHUNK_BYTES  (DCHUNK * SS * 4)           // 65536 (one tensor)
#define STAGE_FLOATS (DCHUNK * SS)               // 16384

// smem (floats):
//  buf (k, later v): [2][16384] = 32768
//  rw:   [16 warps][32 rows][33] = 16896   (stride 33: odd -> conflict-free)
//  logits: [8][516] = 4128
//  mtmp: 32
//  mbar: full[2] (8B each)
#define BUF_OFF   0
#define RW_OFF    32768
#define RW_WARP   (32 * 33)                      // 1056
#define LG_OFF    (RW_OFF + WARPS * RW_WARP)     // 49664
#define LSTRIDE   516
#define MT_OFF    (LG_OFF + 8 * LSTRIDE)         // 53792
#define MBAR_OFF  (MT_OFF + 32)                  // 53824 (even -> 8B aligned)
#define SMEM_BYTES ((MBAR_OFF + 8) * 4)          // 215328 B

typedef unsigned long long ull;

__device__ __forceinline__ ull add2(ull a, ull b) {
    ull c; asm("add.rn.f32x2 %0, %1, %2;" : "=l"(c) : "l"(a), "l"(b)); return c;
}
__device__ __forceinline__ ull fma2(ull a, ull b, ull c) {
    ull d; asm("fma.rn.f32x2 %0, %1, %2, %3;" : "=l"(d) : "l"(a), "l"(b), "l"(c)); return d;
}
__device__ __forceinline__ ull pack2(float x, float y) {
    ull r; asm("mov.b64 %0, {%1, %2};" : "=l"(r) : "f"(x), "f"(y)); return r;
}
__device__ __forceinline__ ull dup2(float x) { return pack2(x, x); }
__device__ __forceinline__ float2 unpack2f(ull a) {
    float2 r; asm("mov.b64 {%0, %1}, %2;" : "=f"(r.x), "=f"(r.y) : "l"(a)); return r;
}

__device__ __forceinline__ void bulk_g2s(void* sdst, const void* gsrc,
                                         unsigned bytes, unsigned mbar) {
    unsigned d = (unsigned)__cvta_generic_to_shared(sdst);
    asm volatile(
        "cp.async.bulk.shared::cluster.global.mbarrier::complete_tx::bytes "
        "[%0], [%1], %2, [%3];"
        :: "r"(d), "l"(gsrc), "r"(bytes), "r"(mbar) : "memory");
}
__device__ __forceinline__ void mbar_init(unsigned mbar, unsigned count) {
    asm volatile("mbarrier.init.shared.b64 [%0], %1;" :: "r"(mbar), "r"(count) : "memory");
}
__device__ __forceinline__ void mbar_expect_tx(unsigned mbar, unsigned bytes) {
    asm volatile("mbarrier.arrive.expect_tx.shared.b64 _, [%0], %1;"
                 :: "r"(mbar), "r"(bytes) : "memory");
}
__device__ __forceinline__ void mbar_wait(unsigned mbar, unsigned parity) {
    asm volatile(
        "{\n\t"
        ".reg .pred P;\n\t"
        "W%=:\n\t"
        "mbarrier.try_wait.parity.acquire.cta.shared::cta.b64 P, [%0], %1, 0x989680;\n\t"
        "@!P bra W%=;\n\t"
        "}"
        :: "r"(mbar), "r"(parity) : "memory");
}

extern __shared__ __align__(16) float smem[];

__global__ void __launch_bounds__(THREADS, 1)
laplace_attn_kernel(const float* __restrict__ q,
                    const float* __restrict__ k,
                    const float* __restrict__ v,
                    float* __restrict__ out)
{
    float* buf    = smem + BUF_OFF;              // [2][DCHUNK][SS]  k then v
    float* rwb    = smem + RW_OFF;               // [WARPS][32][33]
    float* logits = smem + LG_OFF;               // [8][516]
    float* mtmp   = smem + MT_OFF;               // [8][2] max; +16: [8][2] sum
    const unsigned mb = (unsigned)__cvta_generic_to_shared(smem + MBAR_OFF);

    const int tid = threadIdx.x;
    const int w   = tid >> 5;                    // warp = d-split (4 d's per chunk)
    const int l   = tid & 31;
    const int n   = blockIdx.x / (CC / 8);
    const int ct  = blockIdx.x % (CC / 8);
    const int c0  = ct * 8;                      // this block's 8 rows (all per warp)

    float* rw = rwb + w * RW_WARP;

    const float* kbase = k + (size_t)n * CC * SS;
    const float* vbase = v + (size_t)n * CC * SS;

    // prologue: init barriers; stage k chunk 0 into buffer 0
    if (tid == 0) {
        mbar_init(mb,     1);
        mbar_init(mb + 8, 1);
        asm volatile("fence.proxy.async.shared::cta;" ::: "memory");
        mbar_expect_tx(mb, CHUNK_BYTES);
        bulk_g2s(buf, kbase, CHUNK_BYTES, mb);
    }

    // Lane's s-slice: {4l..4l+3} and {128+4l..128+4l+3} (conflict-free LDS.128)
    // ALL 8 rows of the block, negated+packed.
    ull nq[8][4];
#pragma unroll
    for (int r = 0; r < 8; r++) {
        const float* qp = q + ((size_t)n * CC + c0 + r) * SS;
        float4 a = *(const float4*)(qp + 4 * l);
        float4 b = *(const float4*)(qp + 128 + 4 * l);
        nq[r][0] = pack2(-a.x, -a.y);
        nq[r][1] = pack2(-a.z, -a.w);
        nq[r][2] = pack2(-b.x, -b.y);
        nq[r][3] = pack2(-b.z, -b.w);
    }

    __syncthreads();   // barrier init visible before any wait

    // ================= pass 1: distances -> raw logits =================
#pragma unroll 1
    for (int ch = 0; ch < NKCH; ch++) {
        const int p = ch & 1;

        if (ch + 1 < NKCH && tid == 0) {
            mbar_expect_tx(mb + 8u * (1 - p), CHUNK_BYTES);
            bulk_g2s(buf + (1 - p) * STAGE_FLOATS,
                     kbase + (size_t)(ch + 1) * STAGE_FLOATS, CHUNK_BYTES,
                     mb + 8u * (1 - p));
        }
        mbar_wait(mb + 8u * p, (unsigned)((ch >> 1) & 1));

        const float* kc = buf + p * STAGE_FLOATS;

        // ---- distance partials: this warp's 4 d's x ALL 8 rows ----
        // each k word read by exactly ONE warp (no cross-warp redundancy)
#pragma unroll
        for (int dl = 0; dl < 4; dl++) {
            const int d = w * 4 + dl;
            const ulonglong2 ka = *(const ulonglong2*)(kc + d * SS + 4 * l);
            const ulonglong2 kb = *(const ulonglong2*)(kc + d * SS + 128 + 4 * l);
#pragma unroll
            for (int r = 0; r < 8; r++) {
                const float2 f0 = unpack2f(add2(ka.x, nq[r][0]));
                const float2 f1 = unpack2f(add2(ka.y, nq[r][1]));
                const float2 f2 = unpack2f(add2(kb.x, nq[r][2]));
                const float2 f3 = unpack2f(add2(kb.y, nq[r][3]));
                const float s0 = fabsf(f0.x) + fabsf(f0.y);
                const float s1 = fabsf(f1.x) + fabsf(f1.y);
                const float s2 = fabsf(f2.x) + fabsf(f2.y);
                const float s3 = fabsf(f3.x) + fabsf(f3.y);
                // writer-lane-major, stride 33 (odd): bank = (l + e) % 32, CF
                rw[33 * l + r * 4 + dl] = (s0 + s1) + (s2 + s3);
            }
        }
        __syncwarp();

        // ---- reduce: lane l owns entry e=l (r=l>>2, dl=l&3); full 32-sum,
        //      NO shfl needed. bank = (j + l) % 32, conflict-free. ----
        float t0 = 0.f, t1 = 0.f, t2 = 0.f, t3 = 0.f;
#pragma unroll
        for (int j = 0; j < 32; j += 4) {
            t0 += rw[33 * (j + 0) + l];
            t1 += rw[33 * (j + 1) + l];
            t2 += rw[33 * (j + 2) + l];
            t3 += rw[33 * (j + 3) + l];
        }
        const float dist = (t0 + t1) + (t2 + t3);
        logits[(l >> 2) * LSTRIDE + ch * DCHUNK + w * 4 + (l & 3)]
            = -0.5f * dist;                      // logits = -dist/SCALE, SCALE=2

        __syncthreads();   // releases k buffer p; also orders rw reads/writes
    }

    // v prefetch: both buffers provably free after the final pass-1 barrier.
    if (tid == 0) {
        mbar_expect_tx(mb, CHUNK_BYTES);
        bulk_g2s(buf, vbase, CHUNK_BYTES, mb);
        mbar_expect_tx(mb + 8, CHUNK_BYTES);
        bulk_g2s(buf + STAGE_FLOATS, vbase + STAGE_FLOATS, CHUNK_BYTES, mb + 8);
    }

    // ================= exact softmax per row (in place -> P) =================
    {
        const int row  = w >> 1;
        const int half = w & 1;
        float* lrow = logits + row * LSTRIDE + half * 256;
        float4 a = *(const float4*)(lrow + 4 * l);
        float4 b = *(const float4*)(lrow + 128 + 4 * l);

        float mx = fmaxf(fmaxf(fmaxf(a.x, a.y), fmaxf(a.z, a.w)),
                         fmaxf(fmaxf(b.x, b.y), fmaxf(b.z, b.w)));
#pragma unroll
        for (int off = 16; off; off >>= 1)
            mx = fmaxf(mx, __shfl_xor_sync(0xffffffffu, mx, off));
        if (l == 0) mtmp[row * 2 + half] = mx;
        __syncthreads();
        const float m = fmaxf(mtmp[row * 2], mtmp[row * 2 + 1]);

        float e0 = __expf(a.x - m), e1 = __expf(a.y - m);
        float e2 = __expf(a.z - m), e3 = __expf(a.w - m);
        float e4 = __expf(b.x - m), e5 = __expf(b.y - m);
        float e6 = __expf(b.z - m), e7 = __expf(b.w - m);
        float s = ((e0 + e1) + (e2 + e3)) + ((e4 + e5) + (e6 + e7));
#pragma unroll
        for (int off = 16; off; off >>= 1)
            s += __shfl_xor_sync(0xffffffffu, s, off);
        if (l == 0) mtmp[16 + row * 2 + half] = s;
        __syncthreads();
        const float inv = 1.f / (mtmp[16 + row * 2] + mtmp[16 + row * 2 + 1]);

        float4 pa, pb;
        pa.x = e0 * inv; pa.y = e1 * inv; pa.z = e2 * inv; pa.w = e3 * inv;
        pb.x = e4 * inv; pb.y = e5 * inv; pb.z = e6 * inv; pb.w = e7 * inv;
        *(float4*)(lrow + 4 * l)       = pa;     // logits now hold normalized P
        *(float4*)(lrow + 128 + 4 * l) = pb;
    }
    __syncthreads();                             // P visible to all warps

    // ================= pass 2: out = P @ V =================
    ull acc[8][4];
#pragma unroll
    for (int r = 0; r < 8; r++)
#pragma unroll
        for (int j = 0; j < 4; j++) acc[r][j] = 0ULL;

#pragma unroll 1
    for (int j = 0; j < NKCH; j++) {
        const int p = j & 1;
        // k used each buffer's barrier 4x (even) -> fresh-equivalent parity
        mbar_wait(mb + 8u * p, (unsigned)((j >> 1) & 1));

        const float* vc = buf + p * STAGE_FLOATS;

#pragma unroll
        for (int dl = 0; dl < 4; dl++) {
            const int d = w * 4 + dl;
            const ulonglong2 va = *(const ulonglong2*)(vc + d * SS + 4 * l);
            const ulonglong2 vb = *(const ulonglong2*)(vc + d * SS + 128 + 4 * l);
            const float* pcol = logits + j * DCHUNK + w * 4 + dl;
#pragma unroll
            for (int r = 0; r < 8; r++) {
                const ull p2 = dup2(pcol[r * LSTRIDE]);  // broadcast scalar LDS
                acc[r][0] = fma2(p2, va.x, acc[r][0]);
                acc[r][1] = fma2(p2, va.y, acc[r][1]);
                acc[r][2] = fma2(p2, vb.x, acc[r][2]);
                acc[r][3] = fma2(p2, vb.y, acc[r][3]);
            }
        }

        __syncthreads();                         // releases v buffer p

        if (tid == 0 && j + 2 < NKCH) {
            mbar_expect_tx(mb + 8u * p, CHUNK_BYTES);
            bulk_g2s(buf + p * STAGE_FLOATS,
                     vbase + (size_t)(j + 2) * STAGE_FLOATS, CHUNK_BYTES,
                     mb + 8u * p);
        }
    }

    // ================= epilogue: pure sum over the 16 d-splits =================
    float* accbuf = smem;                        // [8 rows][16 splits][256] = 128KB
#pragma unroll
    for (int r = 0; r < 8; r++) {
        float* dst = accbuf + (r * 16 + w) * 256;
        *(ulonglong2*)(dst + 4 * l)       = make_ulonglong2(acc[r][0], acc[r][1]);
        *(ulonglong2*)(dst + 128 + 4 * l) = make_ulonglong2(acc[r][2], acc[r][3]);
    }
    __syncthreads();

    {
        const int row  = w >> 1;
        const int half = w & 1;
        const int sb   = half * 128 + l * 4;

        ull o0 = 0ULL, o1 = 0ULL;
#pragma unroll
        for (int i = 0; i < 16; i++) {
            const ulonglong2 a = *(const ulonglong2*)(accbuf + (row * 16 + i) * 256 + sb);
            o0 = add2(o0, a.x);
            o1 = add2(o1, a.y);
        }
        const int c = ct * 8 + row;
        *(ulonglong2*)(out + ((size_t)n * CC + c) * SS + sb) = make_ulonglong2(o0, o1);
    }
}

extern "C" void kernel_launch(void* const* d_in, const int* in_sizes, int n_in,
                              void* d_out, int out_size) {
    const float* q = (const float*)d_in[0];
    const float* k = (const float*)d_in[1];
    const float* v = (const float*)d_in[2];
    float* out = (float*)d_out;

    cudaFuncSetAttribute(laplace_attn_kernel,
                         cudaFuncAttributeMaxDynamicSharedMemorySize, SMEM_BYTES);

    laplace_attn_kernel<<<NB * (CC / 8), THREADS, SMEM_BYTES>>>(q, k, v, out);
}

// round 14
// speedup vs baseline: 1.0817x; 1.0817x over previous
#include <cuda_runtime.h>

#define NB      2
#define CC      512
#define SS      256
#define DCHUNK  64
#define NKCH    8
#define THREADS 512
#define WARPS   16

#define CHUNK_BYTES  (DCHUNK * SS * 4)           // 65536 (one tensor)
#define STAGE_FLOATS (DCHUNK * SS)               // 16384

// smem (floats):
//  buf (k, later v): [2][16384] = 32768
//  rw:   [16 warps][32 entries][33] = 16896  (stride 33 -> conflict-free)
//  logits: [8][516] = 4128
//  mtmp: 32
//  mbar: full[2] (8B each)
#define BUF_OFF   0
#define RW_OFF    32768
#define RW_WARP   (32 * 33)                      // 1056
#define LG_OFF    (RW_OFF + WARPS * RW_WARP)     // 49664
#define LSTRIDE   516
#define MT_OFF    (LG_OFF + 8 * LSTRIDE)         // 53792
#define MBAR_OFF  (MT_OFF + 32)                  // 53824 (even -> 8B aligned)
#define SMEM_BYTES ((MBAR_OFF + 8) * 4)          // 215328 B

typedef unsigned long long ull;

__device__ __forceinline__ ull add2(ull a, ull b) {
    ull c; asm("add.rn.f32x2 %0, %1, %2;" : "=l"(c) : "l"(a), "l"(b)); return c;
}
__device__ __forceinline__ ull fma2(ull a, ull b, ull c) {
    ull d; asm("fma.rn.f32x2 %0, %1, %2, %3;" : "=l"(d) : "l"(a), "l"(b), "l"(c)); return d;
}
__device__ __forceinline__ ull pack2(float x, float y) {
    ull r; asm("mov.b64 %0, {%1, %2};" : "=l"(r) : "f"(x), "f"(y)); return r;
}
__device__ __forceinline__ ull dup2(float x) { return pack2(x, x); }
__device__ __forceinline__ float2 unpack2f(ull a) {
    float2 r; asm("mov.b64 {%0, %1}, %2;" : "=f"(r.x), "=f"(r.y) : "l"(a)); return r;
}

__device__ __forceinline__ void bulk_g2s(void* sdst, const void* gsrc,
                                         unsigned bytes, unsigned mbar) {
    unsigned d = (unsigned)__cvta_generic_to_shared(sdst);
    asm volatile(
        "cp.async.bulk.shared::cluster.global.mbarrier::complete_tx::bytes "
        "[%0], [%1], %2, [%3];"
        :: "r"(d), "l"(gsrc), "r"(bytes), "r"(mbar) : "memory");
}
__device__ __forceinline__ void mbar_init(unsigned mbar, unsigned count) {
    asm volatile("mbarrier.init.shared.b64 [%0], %1;" :: "r"(mbar), "r"(count) : "memory");
}
__device__ __forceinline__ void mbar_expect_tx(unsigned mbar, unsigned bytes) {
    asm volatile("mbarrier.arrive.expect_tx.shared.b64 _, [%0], %1;"
                 :: "r"(mbar), "r"(bytes) : "memory");
}
__device__ __forceinline__ void mbar_wait(unsigned mbar, unsigned parity) {
    asm volatile(
        "{\n\t"
        ".reg .pred P;\n\t"
        "W%=:\n\t"
        "mbarrier.try_wait.parity.acquire.cta.shared::cta.b64 P, [%0], %1, 0x989680;\n\t"
        "@!P bra W%=;\n\t"
        "}"
        :: "r"(mbar), "r"(parity) : "memory");
}

extern __shared__ __align__(16) float smem[];

__global__ void __launch_bounds__(THREADS, 1)
laplace_attn_kernel(const float* __restrict__ q,
                    const float* __restrict__ k,
                    const float* __restrict__ v,
                    float* __restrict__ out)
{
    float* buf    = smem + BUF_OFF;              // [2][DCHUNK][SS]  k then v
    float* rwb    = smem + RW_OFF;               // [WARPS][32][33]
    float* logits = smem + LG_OFF;               // [8][516]
    float* mtmp   = smem + MT_OFF;               // [8][2] max; +16: [8][2] sum
    const unsigned mb = (unsigned)__cvta_generic_to_shared(smem + MBAR_OFF);

    const int tid = threadIdx.x;
    const int w   = tid >> 5;
    const int l   = tid & 31;
    const int g   = w & 1;                       // row-group (4 rows each)
    const int ds  = w >> 1;                      // d-split 0..7 (8 d's per 64-chunk)
    const int n   = blockIdx.x / (CC / 8);
    const int ct  = blockIdx.x % (CC / 8);
    const int c0  = ct * 8 + g * 4;

    float* rw = rwb + w * RW_WARP;

    const float* kbase = k + (size_t)n * CC * SS;
    const float* vbase = v + (size_t)n * CC * SS;

    // prologue: init barriers; stage k chunk 0 into buffer 0
    if (tid == 0) {
        mbar_init(mb,     1);
        mbar_init(mb + 8, 1);
        asm volatile("fence.proxy.async.shared::cta;" ::: "memory");
        mbar_expect_tx(mb, CHUNK_BYTES);
        bulk_g2s(buf, kbase, CHUNK_BYTES, mb);
    }

    // Lane's s-slice: {4l..4l+3} and {128+4l..128+4l+3} (conflict-free LDS.128)
    ull nq[4][4];
#pragma unroll
    for (int r = 0; r < 4; r++) {
        const float* qp = q + ((size_t)n * CC + c0 + r) * SS;
        float4 a = *(const float4*)(qp + 4 * l);
        float4 b = *(const float4*)(qp + 128 + 4 * l);
        nq[r][0] = pack2(-a.x, -a.y);
        nq[r][1] = pack2(-a.z, -a.w);
        nq[r][2] = pack2(-b.x, -b.y);
        nq[r][3] = pack2(-b.z, -b.w);
    }

    __syncthreads();   // barrier init visible before any wait

    // ================= pass 1: distances -> raw logits =================
#pragma unroll 1
    for (int ch = 0; ch < NKCH; ch++) {
        const int p = ch & 1;

        // stage next k chunk into other buffer (released by ch-1's syncthreads)
        if (ch + 1 < NKCH && tid == 0) {
            mbar_expect_tx(mb + 8u * (1 - p), CHUNK_BYTES);
            bulk_g2s(buf + (1 - p) * STAGE_FLOATS,
                     kbase + (size_t)(ch + 1) * STAGE_FLOATS, CHUNK_BYTES,
                     mb + 8u * (1 - p));
        }
        mbar_wait(mb + 8u * p, (unsigned)((ch >> 1) & 1));

        const float* kc = buf + p * STAGE_FLOATS;

        // ---- distance partials: 8 d's x 4 rows -> 32 entries, one phase ----
        // write bank = (e + l) % 32 : conflict-free permutation
#pragma unroll
        for (int dl = 0; dl < 8; dl++) {
            const int d = ds * 8 + dl;
            const ulonglong2 ka = *(const ulonglong2*)(kc + d * SS + 4 * l);
            const ulonglong2 kb = *(const ulonglong2*)(kc + d * SS + 128 + 4 * l);
#pragma unroll
            for (int r = 0; r < 4; r++) {
                const float2 f0 = unpack2f(add2(ka.x, nq[r][0]));
                const float2 f1 = unpack2f(add2(ka.y, nq[r][1]));
                const float2 f2 = unpack2f(add2(kb.x, nq[r][2]));
                const float2 f3 = unpack2f(add2(kb.y, nq[r][3]));
                const float s0 = fabsf(f0.x) + fabsf(f0.y);
                const float s1 = fabsf(f1.x) + fabsf(f1.y);
                const float s2 = fabsf(f2.x) + fabsf(f2.y);
                const float s3 = fabsf(f3.x) + fabsf(f3.y);
                rw[(r * 8 + dl) * 33 + l] = (s0 + s1) + (s2 + s3);
            }
        }
        __syncwarp();

        // ---- reduce: lane l owns entry l (r = l>>3, dl = l&7) ----
        // full 32-partial sum, no shfl; read bank = (l + j) % 32, CF
        float t0 = 0.f, t1 = 0.f, t2 = 0.f, t3 = 0.f;
#pragma unroll
        for (int j = 0; j < 32; j += 4) {
            t0 += rw[l * 33 + j + 0];
            t1 += rw[l * 33 + j + 1];
            t2 += rw[l * 33 + j + 2];
            t3 += rw[l * 33 + j + 3];
        }
        const float dist = (t0 + t1) + (t2 + t3);
        logits[(g * 4 + (l >> 3)) * LSTRIDE + ch * DCHUNK + ds * 8 + (l & 7)]
            = -0.5f * dist;                      // logits = -dist/SCALE, SCALE=2

        __syncthreads();   // releases k buffer p; orders rw across chunks
    }

    // v prefetch: both buffers provably free after the final pass-1 barrier.
    // Loads overlap the softmax phase below.
    if (tid == 0) {
        mbar_expect_tx(mb, CHUNK_BYTES);
        bulk_g2s(buf, vbase, CHUNK_BYTES, mb);
        mbar_expect_tx(mb + 8, CHUNK_BYTES);
        bulk_g2s(buf + STAGE_FLOATS, vbase + STAGE_FLOATS, CHUNK_BYTES, mb + 8);
    }

    // ================= exact softmax per row (in place -> P) =================
    {
        const int row  = w >> 1;
        const int half = w & 1;
        float* lrow = logits + row * LSTRIDE + half * 256;
        float4 a = *(const float4*)(lrow + 4 * l);
        float4 b = *(const float4*)(lrow + 128 + 4 * l);

        float mx = fmaxf(fmaxf(fmaxf(a.x, a.y), fmaxf(a.z, a.w)),
                         fmaxf(fmaxf(b.x, b.y), fmaxf(b.z, b.w)));
#pragma unroll
        for (int off = 16; off; off >>= 1)
            mx = fmaxf(mx, __shfl_xor_sync(0xffffffffu, mx, off));
        if (l == 0) mtmp[row * 2 + half] = mx;
        __syncthreads();
        const float m = fmaxf(mtmp[row * 2], mtmp[row * 2 + 1]);

        float e0 = __expf(a.x - m), e1 = __expf(a.y - m);
        float e2 = __expf(a.z - m), e3 = __expf(a.w - m);
        float e4 = __expf(b.x - m), e5 = __expf(b.y - m);
        float e6 = __expf(b.z - m), e7 = __expf(b.w - m);
        float s = ((e0 + e1) + (e2 + e3)) + ((e4 + e5) + (e6 + e7));
#pragma unroll
        for (int off = 16; off; off >>= 1)
            s += __shfl_xor_sync(0xffffffffu, s, off);
        if (l == 0) mtmp[16 + row * 2 + half] = s;
        __syncthreads();
        const float inv = 1.f / (mtmp[16 + row * 2] + mtmp[16 + row * 2 + 1]);

        float4 pa, pb;
        pa.x = e0 * inv; pa.y = e1 * inv; pa.z = e2 * inv; pa.w = e3 * inv;
        pb.x = e4 * inv; pb.y = e5 * inv; pb.z = e6 * inv; pb.w = e7 * inv;
        *(float4*)(lrow + 4 * l)       = pa;     // logits now hold normalized P
        *(float4*)(lrow + 128 + 4 * l) = pb;
    }
    __syncthreads();                             // P visible to all warps

    // ================= pass 2: out = P @ V =================
    ull acc[4][4];
#pragma unroll
    for (int r = 0; r < 4; r++)
#pragma unroll
        for (int j = 0; j < 4; j++) acc[r][j] = 0ULL;

#pragma unroll 1
    for (int j = 0; j < NKCH; j++) {
        const int p = j & 1;
        // k used each buffer's barrier 4x (even) -> fresh-equivalent parity
        mbar_wait(mb + 8u * p, (unsigned)((j >> 1) & 1));

        const float* vc = buf + p * STAGE_FLOATS;

#pragma unroll
        for (int grp = 0; grp < 2; grp++) {
            // P for this warp: rows g*4..+3, cols j*64+ds*8+grp*4..+3
            float pj[4][4];
#pragma unroll
            for (int r = 0; r < 4; r++) {
                const float4 pr = *(const float4*)(logits + (g * 4 + r) * LSTRIDE
                                                   + j * DCHUNK + ds * 8 + grp * 4);
                pj[r][0] = pr.x; pj[r][1] = pr.y; pj[r][2] = pr.z; pj[r][3] = pr.w;
            }
#pragma unroll
            for (int dl = 0; dl < 4; dl++) {
                const int d = ds * 8 + grp * 4 + dl;
                const ulonglong2 va = *(const ulonglong2*)(vc + d * SS + 4 * l);
                const ulonglong2 vb = *(const ulonglong2*)(vc + d * SS + 128 + 4 * l);
#pragma unroll
                for (int r = 0; r < 4; r++) {
                    const ull p2 = dup2(pj[r][dl]);
                    acc[r][0] = fma2(p2, va.x, acc[r][0]);
                    acc[r][1] = fma2(p2, va.y, acc[r][1]);
                    acc[r][2] = fma2(p2, vb.x, acc[r][2]);
                    acc[r][3] = fma2(p2, vb.y, acc[r][3]);
                }
            }
        }

        __syncthreads();                         // releases v buffer p

        // refill buffer p with v chunk j+2 (just released by all warps)
        if (tid == 0 && j + 2 < NKCH) {
            mbar_expect_tx(mb + 8u * p, CHUNK_BYTES);
            bulk_g2s(buf + p * STAGE_FLOATS,
                     vbase + (size_t)(j + 2) * STAGE_FLOATS, CHUNK_BYTES,
                     mb + 8u * p);
        }
    }

    // ================= epilogue: pure sum over the 8 d-splits =================
    float* accbuf = smem;                        // [8 rows][8 splits][256] = 64KB
#pragma unroll
    for (int r = 0; r < 4; r++) {
        float* dst = accbuf + ((g * 4 + r) * 8 + ds) * 256;
        *(ulonglong2*)(dst + 4 * l)       = make_ulonglong2(acc[r][0], acc[r][1]);
        *(ulonglong2*)(dst + 128 + 4 * l) = make_ulonglong2(acc[r][2], acc[r][3]);
    }
    __syncthreads();

    {
        const int row  = w >> 1;
        const int half = w & 1;
        const int sb   = half * 128 + l * 4;

        ull o0 = 0ULL, o1 = 0ULL;
#pragma unroll
        for (int i = 0; i < 8; i++) {
            const ulonglong2 a = *(const ulonglong2*)(accbuf + (row * 8 + i) * 256 + sb);
            o0 = add2(o0, a.x);
            o1 = add2(o1, a.y);
        }
        const int c = ct * 8 + row;
        *(ulonglong2*)(out + ((size_t)n * CC + c) * SS + sb) = make_ulonglong2(o0, o1);
    }
}

extern "C" void kernel_launch(void* const* d_in, const int* in_sizes, int n_in,
                              void* d_out, int out_size) {
    const float* q = (const float*)d_in[0];
    const float* k = (const float*)d_in[1];
    const float* v = (const float*)d_in[2];
    float* out = (float*)d_out;

    cudaFuncSetAttribute(laplace_attn_kernel,
                         cudaFuncAttributeMaxDynamicSharedMemorySize, SMEM_BYTES);

    laplace_attn_kernel<<<NB * (CC / 8), THREADS, SMEM_BYTES>>>(q, k, v, out);
}